// round 1
// baseline (speedup 1.0000x reference)
#include <cuda_runtime.h>
#include <math.h>

#define B_  2
#define S_  2048
#define D_  768
#define H_  12
#define DH  64
#define M_  (B_ * S_)      // 4096
#define N_QKV (3 * D_)     // 2304

// Scratch (allocation-free): q/k/v in [B,H,S,Dh], attention out in [B,S,D]
__device__ float g_q[B_ * H_ * S_ * DH];
__device__ float g_k[B_ * H_ * S_ * DH];
__device__ float g_v[B_ * H_ * S_ * DH];
__device__ float g_vw[M_ * D_];

// ---------------------------------------------------------------------------
// Kernel 1: QKV GEMM  C = x(4096x768) @ W(768x2304) + b, scatter to q/k/v
// 64x64 tile, BK=16, 128 threads, each thread 8x4 micro-tile.
// ---------------------------------------------------------------------------
__global__ void qkv_gemm(const float* __restrict__ x,
                         const float* __restrict__ W,
                         const float* __restrict__ bias) {
    __shared__ float As[64][17];
    __shared__ float Bs[16][65];
    const int tid = threadIdx.x;       // 0..127
    const int tr  = tid >> 4;          // 0..7
    const int tc  = tid & 15;          // 0..15
    const int m0  = blockIdx.y * 64;
    const int n0  = blockIdx.x * 64;

    float acc[8][4] = {};

    for (int kt = 0; kt < D_; kt += 16) {
        #pragma unroll
        for (int ii = 0; ii < 8; ii++) {
            int lin = tid + ii * 128;
            int r = lin >> 4, c = lin & 15;
            As[r][c] = x[(size_t)(m0 + r) * D_ + kt + c];
        }
        #pragma unroll
        for (int ii = 0; ii < 8; ii++) {
            int lin = tid + ii * 128;
            int r = lin >> 6, c = lin & 63;
            Bs[r][c] = W[(size_t)(kt + r) * N_QKV + n0 + c];
        }
        __syncthreads();
        #pragma unroll
        for (int kk = 0; kk < 16; kk++) {
            float a[8], b[4];
            #pragma unroll
            for (int i = 0; i < 8; i++) a[i] = As[tr + 8 * i][kk];
            #pragma unroll
            for (int j = 0; j < 4; j++) b[j] = Bs[kk][tc + 16 * j];
            #pragma unroll
            for (int i = 0; i < 8; i++)
                #pragma unroll
                for (int j = 0; j < 4; j++)
                    acc[i][j] += a[i] * b[j];
        }
        __syncthreads();
    }

    #pragma unroll
    for (int i = 0; i < 8; i++) {
        int m  = m0 + tr + 8 * i;
        int bb = m >> 11;            // / 2048
        int s  = m & (S_ - 1);
        #pragma unroll
        for (int j = 0; j < 4; j++) {
            int n = n0 + tc + 16 * j;
            float val = acc[i][j] + bias[n];
            int t   = n / D_;
            int rem = n - t * D_;
            int h   = rem >> 6;
            int d   = rem & 63;
            size_t idx = ((size_t)(bb * H_ + h) * S_ + s) * DH + d;
            if (t == 0)      g_q[idx] = val;
            else if (t == 1) g_k[idx] = val;
            else             g_v[idx] = val;
        }
    }
}

// ---------------------------------------------------------------------------
// Kernel 2: flash attention, causal + key mask.
// One block per (q-tile of 64, b*h). 128 threads; thread (r,c) r=tid/8, c=tid%8.
// Logit tile: rows {r,r+16,r+32,r+48} x cols {8c..8c+7}.
// ---------------------------------------------------------------------------
__global__ void attn_kernel(const int* __restrict__ mask) {
    extern __shared__ float sm[];
    float (*Qs)[65] = (float(*)[65])sm;                 // 64x65
    float (*Ks)[65] = (float(*)[65])(sm + 64 * 65);     // 64x65
    float (*Vs)[65] = (float(*)[65])(sm + 2 * 64 * 65); // 64x65
    float (*Ps)[65] = (float(*)[65])(sm + 3 * 64 * 65); // 64x65
    float* arow     = sm + 4 * 64 * 65;                 // 64
    float* mneg     = arow + 64;                        // 64

    const int tid = threadIdx.x;
    const int r   = tid >> 3;   // 0..15
    const int c   = tid & 7;    // 0..7
    const int bh  = blockIdx.y;
    const int b   = bh / H_;
    const int h   = bh - b * H_;
    const int q0  = blockIdx.x * 64;

    const float* qbase = g_q + (size_t)bh * S_ * DH;
    const float* kbase = g_k + (size_t)bh * S_ * DH;
    const float* vbase = g_v + (size_t)bh * S_ * DH;

    #pragma unroll 8
    for (int ii = 0; ii < 32; ii++) {
        int lin = tid + ii * 128;
        int rr = lin >> 6, cc = lin & 63;
        Qs[rr][cc] = qbase[(size_t)(q0 + rr) * DH + cc];
    }

    float m_i[4], l_i[4], o[4][8];
    #pragma unroll
    for (int i = 0; i < 4; i++) {
        m_i[i] = -INFINITY; l_i[i] = 0.f;
        #pragma unroll
        for (int j = 0; j < 8; j++) o[i][j] = 0.f;
    }

    for (int k0 = 0; k0 <= q0; k0 += 64) {
        __syncthreads();   // protect Ks/Vs/Ps from previous iteration readers
        #pragma unroll 8
        for (int ii = 0; ii < 32; ii++) {
            int lin = tid + ii * 128;
            int rr = lin >> 6, cc = lin & 63;
            Ks[rr][cc] = kbase[(size_t)(k0 + rr) * DH + cc];
            Vs[rr][cc] = vbase[(size_t)(k0 + rr) * DH + cc];
        }
        if (tid < 64)
            mneg[tid] = (mask[b * S_ + k0 + tid] != 0) ? 0.f : -INFINITY;
        __syncthreads();

        // ---- S = Q @ K^T ----
        float sacc[4][8] = {};
        #pragma unroll 8
        for (int kk = 0; kk < 64; kk++) {
            float qf[4], kf[8];
            #pragma unroll
            for (int i = 0; i < 4; i++) qf[i] = Qs[r + 16 * i][kk];
            #pragma unroll
            for (int j = 0; j < 8; j++) kf[j] = Ks[c * 8 + j][kk];
            #pragma unroll
            for (int i = 0; i < 4; i++)
                #pragma unroll
                for (int j = 0; j < 8; j++)
                    sacc[i][j] += qf[i] * kf[j];
        }

        // ---- scale + mask + online softmax ----
        float alpha_[4];
        #pragma unroll
        for (int i = 0; i < 4; i++) {
            int srow = q0 + r + 16 * i;
            float rmax = -INFINITY;
            #pragma unroll
            for (int j = 0; j < 8; j++) {
                int z = k0 + c * 8 + j;
                float v = sacc[i][j] * 0.125f + mneg[c * 8 + j];
                v = (z <= srow) ? v : -INFINITY;
                sacc[i][j] = v;
                rmax = fmaxf(rmax, v);
            }
            #pragma unroll
            for (int st = 1; st < 8; st <<= 1)
                rmax = fmaxf(rmax, __shfl_xor_sync(0xffffffffu, rmax, st));
            float mnew = fmaxf(m_i[i], rmax);
            float alpha;
            float rsum = 0.f;
            if (mnew == -INFINITY) {
                alpha = 1.f;
                #pragma unroll
                for (int j = 0; j < 8; j++) sacc[i][j] = 0.f;
            } else {
                alpha = __expf(m_i[i] - mnew);
                #pragma unroll
                for (int j = 0; j < 8; j++) {
                    float p = __expf(sacc[i][j] - mnew);
                    sacc[i][j] = p;
                    rsum += p;
                }
            }
            #pragma unroll
            for (int st = 1; st < 8; st <<= 1)
                rsum += __shfl_xor_sync(0xffffffffu, rsum, st);
            l_i[i] = l_i[i] * alpha + rsum;
            m_i[i] = mnew;
            alpha_[i] = alpha;
        }

        // stage P + per-row alpha
        #pragma unroll
        for (int i = 0; i < 4; i++) {
            #pragma unroll
            for (int j = 0; j < 8; j++)
                Ps[r + 16 * i][c * 8 + j] = sacc[i][j];
            if (c == 0) arow[r + 16 * i] = alpha_[i];
        }
        __syncthreads();

        // ---- O = O*alpha + P @ V ----
        #pragma unroll
        for (int i = 0; i < 4; i++) {
            float al = arow[r + 16 * i];
            #pragma unroll
            for (int j = 0; j < 8; j++) o[i][j] *= al;
        }
        #pragma unroll 8
        for (int jj = 0; jj < 64; jj++) {
            float pv[4], vv[8];
            #pragma unroll
            for (int i = 0; i < 4; i++) pv[i] = Ps[r + 16 * i][jj];
            #pragma unroll
            for (int j = 0; j < 8; j++) vv[j] = Vs[jj][c * 8 + j];
            #pragma unroll
            for (int i = 0; i < 4; i++)
                #pragma unroll
                for (int j = 0; j < 8; j++)
                    o[i][j] += pv[i] * vv[j];
        }
    }

    // write [b, s, h, d] row-major (== (B,S,D))
    #pragma unroll
    for (int i = 0; i < 4; i++) {
        int s = q0 + r + 16 * i;
        float inv = 1.f / l_i[i];
        #pragma unroll
        for (int j = 0; j < 8; j++) {
            int d = c * 8 + j;
            g_vw[((size_t)(b * S_ + s)) * D_ + h * DH + d] = o[i][j] * inv;
        }
    }
}

// ---------------------------------------------------------------------------
// Kernel 3: output GEMM  out = vw(4096x768) @ W(768x768) + b
// ---------------------------------------------------------------------------
__global__ void out_gemm(const float* __restrict__ W,
                         const float* __restrict__ bias,
                         float* __restrict__ out) {
    __shared__ float As[64][17];
    __shared__ float Bs[16][65];
    const int tid = threadIdx.x;
    const int tr  = tid >> 4;
    const int tc  = tid & 15;
    const int m0  = blockIdx.y * 64;
    const int n0  = blockIdx.x * 64;

    float acc[8][4] = {};

    for (int kt = 0; kt < D_; kt += 16) {
        #pragma unroll
        for (int ii = 0; ii < 8; ii++) {
            int lin = tid + ii * 128;
            int r = lin >> 4, c = lin & 15;
            As[r][c] = g_vw[(size_t)(m0 + r) * D_ + kt + c];
        }
        #pragma unroll
        for (int ii = 0; ii < 8; ii++) {
            int lin = tid + ii * 128;
            int r = lin >> 6, c = lin & 63;
            Bs[r][c] = W[(size_t)(kt + r) * D_ + n0 + c];
        }
        __syncthreads();
        #pragma unroll
        for (int kk = 0; kk < 16; kk++) {
            float a[8], b[4];
            #pragma unroll
            for (int i = 0; i < 8; i++) a[i] = As[tr + 8 * i][kk];
            #pragma unroll
            for (int j = 0; j < 4; j++) b[j] = Bs[kk][tc + 16 * j];
            #pragma unroll
            for (int i = 0; i < 8; i++)
                #pragma unroll
                for (int j = 0; j < 4; j++)
                    acc[i][j] += a[i] * b[j];
        }
        __syncthreads();
    }

    #pragma unroll
    for (int i = 0; i < 8; i++) {
        int m = m0 + tr + 8 * i;
        #pragma unroll
        for (int j = 0; j < 4; j++) {
            int n = n0 + tc + 16 * j;
            out[(size_t)m * D_ + n] = acc[i][j] + bias[n];
        }
    }
}

// ---------------------------------------------------------------------------
extern "C" void kernel_launch(void* const* d_in, const int* in_sizes, int n_in,
                              void* d_out, int out_size) {
    const float* x    = (const float*)d_in[0];
    const float* Wqkv = (const float*)d_in[1];
    const float* bqkv = (const float*)d_in[2];
    const float* Wvw  = (const float*)d_in[3];
    const float* bvw  = (const float*)d_in[4];
    const int*   mask = (const int*)d_in[5];
    float* out = (float*)d_out;

    const int attn_smem = (4 * 64 * 65 + 128) * (int)sizeof(float);  // 67,584 B
    cudaFuncSetAttribute(attn_kernel, cudaFuncAttributeMaxDynamicSharedMemorySize,
                         attn_smem);

    dim3 g1(N_QKV / 64, M_ / 64);    // 36 x 64
    qkv_gemm<<<g1, 128>>>(x, Wqkv, bqkv);

    dim3 g2(S_ / 64, B_ * H_);       // 32 x 24
    attn_kernel<<<g2, 128, attn_smem>>>(mask);

    dim3 g3(D_ / 64, M_ / 64);       // 12 x 64
    out_gemm<<<g3, 128>>>(Wvw, bvw, out);
}

// round 2
// speedup vs baseline: 1.4470x; 1.4470x over previous
#include <cuda_runtime.h>
#include <math.h>

#define B_  2
#define S_  2048
#define D_  768
#define H_  12
#define DH  64
#define M_  (B_ * S_)      // 4096
#define N_QKV (3 * D_)     // 2304

typedef unsigned long long u64;

__device__ __forceinline__ u64 pk2(float v) {
    u64 r; asm("mov.b64 %0, {%1, %1};" : "=l"(r) : "f"(v)); return r;
}
__device__ __forceinline__ void fma2(u64& d, u64 a, u64 b) {
    asm("fma.rn.f32x2 %0, %1, %2, %0;" : "+l"(d) : "l"(a), "l"(b));
}
__device__ __forceinline__ void mul2(u64& d, u64 a) {
    asm("mul.rn.f32x2 %0, %0, %1;" : "+l"(d) : "l"(a));
}
__device__ __forceinline__ float2 up2(u64 v) {
    float2 f; asm("mov.b64 {%0, %1}, %2;" : "=f"(f.x), "=f"(f.y) : "l"(v)); return f;
}

// Scratch (allocation-free)
__device__ float g_q[B_ * H_ * S_ * DH];
__device__ float g_k[B_ * H_ * S_ * DH];
__device__ float g_v[B_ * H_ * S_ * DH];
__device__ float g_vw[M_ * D_];

// ---------------------------------------------------------------------------
// Kernel 1: QKV GEMM  C = x(4096x768) @ W(768x2304) + b, scatter to q/k/v.
// 64x128 tile, BK=16, 128 threads. Thread: 8 rows x 4 col-pairs, f32x2 FMA.
// ---------------------------------------------------------------------------
__global__ void __launch_bounds__(128) qkv_gemm(const float* __restrict__ x,
                                                const float* __restrict__ W,
                                                const float* __restrict__ bias) {
    __shared__ float As[64][17];
    __shared__ float Bs[16][132];       // stride 132 -> 16B-aligned rows
    const int tid = threadIdx.x;
    const int tr  = tid >> 4;           // 0..7
    const int tc  = tid & 15;           // 0..15
    const int m0  = blockIdx.y * 64;
    const int n0  = blockIdx.x * 128;

    u64 acc[8][4] = {};

    for (int kt = 0; kt < D_; kt += 16) {
        #pragma unroll
        for (int ii = 0; ii < 2; ii++) {              // A: 64x16
            int f = tid + ii * 128;
            int r = f >> 2, c4 = (f & 3) * 4;
            float4 v = *(const float4*)&x[(size_t)(m0 + r) * D_ + kt + c4];
            As[r][c4 + 0] = v.x; As[r][c4 + 1] = v.y;
            As[r][c4 + 2] = v.z; As[r][c4 + 3] = v.w;
        }
        #pragma unroll
        for (int ii = 0; ii < 4; ii++) {              // B: 16x128
            int f = tid + ii * 128;
            int r = f >> 5, c4 = (f & 31) * 4;
            *(float4*)&Bs[r][c4] =
                *(const float4*)&W[(size_t)(kt + r) * N_QKV + n0 + c4];
        }
        __syncthreads();
        #pragma unroll
        for (int kk = 0; kk < 16; kk++) {
            u64 b[4];
            #pragma unroll
            for (int j = 0; j < 4; j++)
                b[j] = *(const u64*)&Bs[kk][2 * (tc + 16 * j)];
            #pragma unroll
            for (int i = 0; i < 8; i++) {
                u64 a = pk2(As[tr + 8 * i][kk]);
                #pragma unroll
                for (int j = 0; j < 4; j++) fma2(acc[i][j], a, b[j]);
            }
        }
        __syncthreads();
    }

    #pragma unroll
    for (int i = 0; i < 8; i++) {
        int m  = m0 + tr + 8 * i;
        int bb = m >> 11;
        int s  = m & (S_ - 1);
        #pragma unroll
        for (int j = 0; j < 4; j++) {
            float2 p = up2(acc[i][j]);
            #pragma unroll
            for (int u = 0; u < 2; u++) {
                int n = n0 + 2 * (tc + 16 * j) + u;
                float val = (u ? p.y : p.x) + bias[n];
                int t   = n / D_;
                int rem = n - t * D_;
                int h   = rem >> 6;
                int d   = rem & 63;
                size_t idx = ((size_t)(bb * H_ + h) * S_ + s) * DH + d;
                if (t == 0)      g_q[idx] = val;
                else if (t == 1) g_k[idx] = val;
                else             g_v[idx] = val;
            }
        }
    }
}

// ---------------------------------------------------------------------------
// Kernel 2: flash attention, causal + key mask, f32x2 inner products.
// 128 threads: r = tid/8 (0..15), c = tid%8. Thread owns rows {r+16i} and
// col-pairs {2*(c+8j), +1} for j=0..3 (interleaved to avoid LDS.64 conflicts).
// ---------------------------------------------------------------------------
__global__ void __launch_bounds__(128) attn_kernel(const int* __restrict__ mask) {
    extern __shared__ float sm[];
    float (*Qs)[65] = (float(*)[65])sm;                       // 64x65
    float (*Kt)[66] = (float(*)[66])(sm + 64 * 65);           // 64x66 (dh-major)
    float (*Vs)[66] = (float(*)[66])(sm + 64 * 65 + 64 * 66); // 64x66
    float (*Ps)[66] = (float(*)[66])(sm + 64 * 65 + 2 * 64 * 66);
    float* arow     = sm + 64 * 65 + 3 * 64 * 66;             // 64
    float* mneg     = arow + 64;                              // 64

    const int tid = threadIdx.x;
    const int r   = tid >> 3;   // 0..15
    const int c   = tid & 7;    // 0..7
    const int bh  = blockIdx.y;
    const int b   = bh / H_;
    const int h   = bh - b * H_;
    const int q0  = blockIdx.x * 64;

    const float* qbase = g_q + (size_t)bh * S_ * DH;
    const float* kbase = g_k + (size_t)bh * S_ * DH;
    const float* vbase = g_v + (size_t)bh * S_ * DH;

    #pragma unroll 8
    for (int ii = 0; ii < 32; ii++) {
        int lin = tid + ii * 128;
        int rr = lin >> 6, cc = lin & 63;
        Qs[rr][cc] = qbase[(size_t)(q0 + rr) * DH + cc];
    }

    float m_i[4], l_i[4];
    u64 o[4][4] = {};
    #pragma unroll
    for (int i = 0; i < 4; i++) { m_i[i] = -INFINITY; l_i[i] = 0.f; }

    for (int k0 = 0; k0 <= q0; k0 += 64) {
        __syncthreads();   // protect Kt/Vs/Ps from prior readers
        #pragma unroll 8
        for (int ii = 0; ii < 32; ii++) {
            int lin = tid + ii * 128;
            int rr = lin >> 6, cc = lin & 63;
            Kt[cc][rr] = kbase[(size_t)(k0 + rr) * DH + cc];  // transpose
            Vs[rr][cc] = vbase[(size_t)(k0 + rr) * DH + cc];
        }
        if (tid < 64)
            mneg[tid] = (mask[b * S_ + k0 + tid] != 0) ? 0.f : -INFINITY;
        __syncthreads();

        // ---- S = Q @ K^T (packed pairs over key dim) ----
        u64 sacc[4][4] = {};
        #pragma unroll 16
        for (int kk = 0; kk < 64; kk++) {
            u64 kf[4];
            #pragma unroll
            for (int j = 0; j < 4; j++)
                kf[j] = *(const u64*)&Kt[kk][2 * (c + 8 * j)];
            #pragma unroll
            for (int i = 0; i < 4; i++) {
                u64 q = pk2(Qs[r + 16 * i][kk]);
                #pragma unroll
                for (int j = 0; j < 4; j++) fma2(sacc[i][j], q, kf[j]);
            }
        }

        // ---- scale + mask + online softmax ----
        #pragma unroll
        for (int i = 0; i < 4; i++) {
            int srow = q0 + r + 16 * i;
            float sv[8];
            float rmax = -INFINITY;
            #pragma unroll
            for (int j = 0; j < 4; j++) {
                float2 p = up2(sacc[i][j]);
                int col = 2 * (c + 8 * j);
                float v0 = p.x * 0.125f + mneg[col];
                float v1 = p.y * 0.125f + mneg[col + 1];
                v0 = (k0 + col     <= srow) ? v0 : -INFINITY;
                v1 = (k0 + col + 1 <= srow) ? v1 : -INFINITY;
                sv[2 * j] = v0; sv[2 * j + 1] = v1;
                rmax = fmaxf(rmax, fmaxf(v0, v1));
            }
            #pragma unroll
            for (int st = 1; st < 8; st <<= 1)
                rmax = fmaxf(rmax, __shfl_xor_sync(0xffffffffu, rmax, st));
            float mnew = fmaxf(m_i[i], rmax);
            float alpha, rsum = 0.f;
            if (mnew == -INFINITY) {
                alpha = 1.f;
                #pragma unroll
                for (int j = 0; j < 8; j++) sv[j] = 0.f;
            } else {
                alpha = __expf(m_i[i] - mnew);
                #pragma unroll
                for (int j = 0; j < 8; j++) {
                    float p = __expf(sv[j] - mnew);
                    sv[j] = p; rsum += p;
                }
            }
            #pragma unroll
            for (int st = 1; st < 8; st <<= 1)
                rsum += __shfl_xor_sync(0xffffffffu, rsum, st);
            l_i[i] = l_i[i] * alpha + rsum;
            m_i[i] = mnew;
            #pragma unroll
            for (int j = 0; j < 4; j++)
                *(float2*)&Ps[r + 16 * i][2 * (c + 8 * j)] =
                    make_float2(sv[2 * j], sv[2 * j + 1]);
            if (c == 0) arow[r + 16 * i] = alpha;
        }
        __syncthreads();

        // ---- O = O*alpha + P @ V ----
        #pragma unroll
        for (int i = 0; i < 4; i++) {
            u64 al = pk2(arow[r + 16 * i]);
            #pragma unroll
            for (int j = 0; j < 4; j++) mul2(o[i][j], al);
        }
        #pragma unroll 16
        for (int jj = 0; jj < 64; jj++) {
            u64 vv[4];
            #pragma unroll
            for (int j = 0; j < 4; j++)
                vv[j] = *(const u64*)&Vs[jj][2 * (c + 8 * j)];
            #pragma unroll
            for (int i = 0; i < 4; i++) {
                u64 p = pk2(Ps[r + 16 * i][jj]);
                #pragma unroll
                for (int j = 0; j < 4; j++) fma2(o[i][j], p, vv[j]);
            }
        }
    }

    #pragma unroll
    for (int i = 0; i < 4; i++) {
        int s = q0 + r + 16 * i;
        float inv = 1.f / l_i[i];
        #pragma unroll
        for (int j = 0; j < 4; j++) {
            float2 p = up2(o[i][j]);
            int d = 2 * (c + 8 * j);
            float* dst = &g_vw[((size_t)(b * S_ + s)) * D_ + h * DH + d];
            dst[0] = p.x * inv;
            dst[1] = p.y * inv;
        }
    }
}

// ---------------------------------------------------------------------------
// Kernel 3: output GEMM  out = vw(4096x768) @ W(768x768) + b, 64x128 tiles.
// ---------------------------------------------------------------------------
__global__ void __launch_bounds__(128) out_gemm(const float* __restrict__ W,
                                                const float* __restrict__ bias,
                                                float* __restrict__ out) {
    __shared__ float As[64][17];
    __shared__ float Bs[16][132];
    const int tid = threadIdx.x;
    const int tr  = tid >> 4;
    const int tc  = tid & 15;
    const int m0  = blockIdx.y * 64;
    const int n0  = blockIdx.x * 128;

    u64 acc[8][4] = {};

    for (int kt = 0; kt < D_; kt += 16) {
        #pragma unroll
        for (int ii = 0; ii < 2; ii++) {
            int f = tid + ii * 128;
            int r = f >> 2, c4 = (f & 3) * 4;
            float4 v = *(const float4*)&g_vw[(size_t)(m0 + r) * D_ + kt + c4];
            As[r][c4 + 0] = v.x; As[r][c4 + 1] = v.y;
            As[r][c4 + 2] = v.z; As[r][c4 + 3] = v.w;
        }
        #pragma unroll
        for (int ii = 0; ii < 4; ii++) {
            int f = tid + ii * 128;
            int r = f >> 5, c4 = (f & 31) * 4;
            *(float4*)&Bs[r][c4] =
                *(const float4*)&W[(size_t)(kt + r) * D_ + n0 + c4];
        }
        __syncthreads();
        #pragma unroll
        for (int kk = 0; kk < 16; kk++) {
            u64 b[4];
            #pragma unroll
            for (int j = 0; j < 4; j++)
                b[j] = *(const u64*)&Bs[kk][2 * (tc + 16 * j)];
            #pragma unroll
            for (int i = 0; i < 8; i++) {
                u64 a = pk2(As[tr + 8 * i][kk]);
                #pragma unroll
                for (int j = 0; j < 4; j++) fma2(acc[i][j], a, b[j]);
            }
        }
        __syncthreads();
    }

    #pragma unroll
    for (int i = 0; i < 8; i++) {
        int m = m0 + tr + 8 * i;
        #pragma unroll
        for (int j = 0; j < 4; j++) {
            float2 p = up2(acc[i][j]);
            int n = n0 + 2 * (tc + 16 * j);
            out[(size_t)m * D_ + n]     = p.x + bias[n];
            out[(size_t)m * D_ + n + 1] = p.y + bias[n + 1];
        }
    }
}

// ---------------------------------------------------------------------------
extern "C" void kernel_launch(void* const* d_in, const int* in_sizes, int n_in,
                              void* d_out, int out_size) {
    const float* x    = (const float*)d_in[0];
    const float* Wqkv = (const float*)d_in[1];
    const float* bqkv = (const float*)d_in[2];
    const float* Wvw  = (const float*)d_in[3];
    const float* bvw  = (const float*)d_in[4];
    const int*   mask = (const int*)d_in[5];
    float* out = (float*)d_out;

    const int attn_smem = (64 * 65 + 3 * 64 * 66 + 128) * (int)sizeof(float); // 67,840 B
    cudaFuncSetAttribute(attn_kernel, cudaFuncAttributeMaxDynamicSharedMemorySize,
                         attn_smem);

    dim3 g1(N_QKV / 128, M_ / 64);   // 18 x 64
    qkv_gemm<<<g1, 128>>>(x, Wqkv, bqkv);

    dim3 g2(S_ / 64, B_ * H_);       // 32 x 24
    attn_kernel<<<g2, 128, attn_smem>>>(mask);

    dim3 g3(D_ / 128, M_ / 64);      // 6 x 64
    out_gemm<<<g3, 128>>>(Wvw, bvw, out);
}

// round 4
// speedup vs baseline: 3.4254x; 2.3673x over previous
#include <cuda_runtime.h>
#include <cuda_bf16.h>
#include <math.h>
#include <stdint.h>

#define B_  2
#define S_  2048
#define D_  768
#define H_  12
#define DH  64
#define M_  (B_ * S_)      // 4096
#define N_QKV (3 * D_)     // 2304
#define LDT 72             // smem tile row stride (bf16 elems), conflict-free ldmatrix

// ---------------- scratch (allocation-free) ----------------
__device__ __nv_bfloat16 g_qh[B_ * H_ * S_ * DH], g_ql[B_ * H_ * S_ * DH];
__device__ __nv_bfloat16 g_kh[B_ * H_ * S_ * DH], g_kl[B_ * H_ * S_ * DH];
__device__ float         g_v [B_ * H_ * S_ * DH];
__device__ float         g_vw[M_ * D_];

__device__ __nv_bfloat16 g_xh[M_ * D_],     g_xl[M_ * D_];
__device__ __nv_bfloat16 g_wqh[N_QKV * D_], g_wql[N_QKV * D_];   // W_qkv^T [N,K]
__device__ __nv_bfloat16 g_wvh[D_ * D_],    g_wvl[D_ * D_];      // W_vw^T  [N,K]
__device__ __nv_bfloat16 g_vwh[M_ * D_],    g_vwl[M_ * D_];

// ---------------- helpers ----------------
__device__ __forceinline__ uint32_t smem_u32(const void* p) {
    uint32_t a;
    asm("{ .reg .u64 t; cvta.to.shared.u64 t, %1; cvt.u32.u64 %0, t; }"
        : "=r"(a) : "l"(p));
    return a;
}
__device__ __forceinline__ void ldsm4(uint32_t* r, uint32_t a) {
    asm volatile("ldmatrix.sync.aligned.m8n8.x4.shared.b16 {%0,%1,%2,%3}, [%4];"
        : "=r"(r[0]), "=r"(r[1]), "=r"(r[2]), "=r"(r[3]) : "r"(a));
}
__device__ __forceinline__ void ldsm4t(uint32_t* r, uint32_t a) {
    asm volatile("ldmatrix.sync.aligned.m8n8.x4.trans.shared.b16 {%0,%1,%2,%3}, [%4];"
        : "=r"(r[0]), "=r"(r[1]), "=r"(r[2]), "=r"(r[3]) : "r"(a));
}
__device__ __forceinline__ void mma16816(float* c, const uint32_t* a, const uint32_t* b) {
    asm volatile("mma.sync.aligned.m16n8k16.row.col.f32.bf16.bf16.f32 "
        "{%0,%1,%2,%3}, {%4,%5,%6,%7}, {%8,%9}, {%0,%1,%2,%3};"
        : "+f"(c[0]), "+f"(c[1]), "+f"(c[2]), "+f"(c[3])
        : "r"(a[0]), "r"(a[1]), "r"(a[2]), "r"(a[3]), "r"(b[0]), "r"(b[1]));
}
// A-frag (m16k16) from row-major smem tile, base in bytes
__device__ __forceinline__ void lda_frag(uint32_t* r, uint32_t base, int row0, int k0, int lane) {
    uint32_t a = base + (uint32_t)(((row0 + (lane & 15)) * LDT + k0 + ((lane >> 4) << 3)) << 1);
    ldsm4(r, a);
}
// B-frags for 2 n8-tiles (n0..n0+15) at kstep k0, from [n][k] row-major smem
__device__ __forceinline__ void ldb_frag2(uint32_t* r, uint32_t base, int n0, int k0, int lane) {
    int g = lane >> 3;
    uint32_t a = base + (uint32_t)(((n0 + ((g & 2) << 2) + (lane & 7)) * LDT
                                    + k0 + ((g & 1) << 3)) << 1);
    ldsm4(r, a);
}
// B-frags for 2 dh8-tiles via transpose from [key][dh] smem (PV)
__device__ __forceinline__ void ldbt_frag2(uint32_t* r, uint32_t base, int key0, int dh0, int lane) {
    int g = lane >> 3;
    uint32_t a = base + (uint32_t)(((key0 + ((g & 1) << 3) + (lane & 7)) * LDT
                                    + dh0 + ((g & 2) << 2)) << 1);
    ldsm4t(r, a);
}
__device__ __forceinline__ void pack_hl(float v0, float v1, uint32_t& hi, uint32_t& lo) {
    __nv_bfloat16 h0 = __float2bfloat16(v0), h1 = __float2bfloat16(v1);
    __nv_bfloat162 hh(h0, h1);
    hi = *(uint32_t*)&hh;
    __nv_bfloat16 l0 = __float2bfloat16(v0 - __bfloat162float(h0));
    __nv_bfloat16 l1 = __float2bfloat16(v1 - __bfloat162float(h1));
    __nv_bfloat162 ll(l0, l1);
    lo = *(uint32_t*)&ll;
}

// ---------------------------------------------------------------------------
// Split fp32 -> bf16 hi + lo
// ---------------------------------------------------------------------------
__global__ void split_kernel(const float* __restrict__ src,
                             __nv_bfloat16* __restrict__ hi,
                             __nv_bfloat16* __restrict__ lo, int n) {
    int i = (blockIdx.x * blockDim.x + threadIdx.x) * 4;
    if (i >= n) return;
    float4 v = *(const float4*)(src + i);
    uint32_t h01, l01, h23, l23;
    pack_hl(v.x, v.y, h01, l01);
    pack_hl(v.z, v.w, h23, l23);
    *(uint32_t*)(hi + i)     = h01;
    *(uint32_t*)(hi + i + 2) = h23;
    *(uint32_t*)(lo + i)     = l01;
    *(uint32_t*)(lo + i + 2) = l23;
}

// ---------------------------------------------------------------------------
// Transpose + split: W[K,N] fp32 -> Wt hi/lo [N,K] bf16
// ---------------------------------------------------------------------------
__global__ void tsplit_kernel(const float* __restrict__ W,
                              __nv_bfloat16* __restrict__ hi,
                              __nv_bfloat16* __restrict__ lo, int K, int N) {
    __shared__ float t[32][33];
    int n0 = blockIdx.x * 32, k0 = blockIdx.y * 32;
    int tx = threadIdx.x, ty = threadIdx.y;
    #pragma unroll
    for (int jj = 0; jj < 4; jj++)
        t[ty + jj * 8][tx] = W[(size_t)(k0 + ty + jj * 8) * N + n0 + tx];
    __syncthreads();
    #pragma unroll
    for (int jj = 0; jj < 4; jj++) {
        float v = t[tx][ty + jj * 8];
        int n = n0 + ty + jj * 8, k = k0 + tx;
        __nv_bfloat16 h = __float2bfloat16(v);
        hi[(size_t)n * K + k] = h;
        lo[(size_t)n * K + k] = __float2bfloat16(v - __bfloat162float(h));
    }
}

// ---------------------------------------------------------------------------
// Projection GEMM: D[128x64] = A[128xK] @ B[N,K]^T + bias, 3-term bf16 split.
// 4 warps, warp tile 64x32 (4 m16 x 4 n8). K chunks of 64.
// SCATTER=1: qkv epilogue -> g_qh/g_ql/g_kh/g_kl (bf16), g_v (fp32).
// SCATTER=0: out = result + bias.
// ---------------------------------------------------------------------------
#define PROJ_SMEM ((2 * 128 * LDT + 2 * 64 * LDT) * 2)   // 55296 bytes

template<int SCATTER>
__global__ void __launch_bounds__(128) mma_gemm(
    const __nv_bfloat16* __restrict__ Ahi, const __nv_bfloat16* __restrict__ Alo,
    const __nv_bfloat16* __restrict__ Bhi, const __nv_bfloat16* __restrict__ Blo,
    const float* __restrict__ bias, float* __restrict__ out, int N) {
    extern __shared__ __nv_bfloat16 sm[];
    __nv_bfloat16* Ah = sm;
    __nv_bfloat16* Al = Ah + 128 * LDT;
    __nv_bfloat16* Bh = Al + 128 * LDT;
    __nv_bfloat16* Bl = Bh + 64 * LDT;
    const uint32_t s_ah = smem_u32(Ah), s_al = smem_u32(Al);
    const uint32_t s_bh = smem_u32(Bh), s_bl = smem_u32(Bl);

    const int tid  = threadIdx.x;
    const int wid  = tid >> 5, lane = tid & 31;
    const int wr   = wid >> 1, wc = wid & 1;
    const int m0   = blockIdx.y * 128;
    const int n0   = blockIdx.x * 64;

    float acc[4][4][4] = {};

    for (int c = 0; c < 12; c++) {
        const int k0 = c * 64;
        __syncthreads();
        #pragma unroll
        for (int it = 0; it < 8; it++) {
            int lin = tid + it * 128;
            int r = lin >> 3, c8 = (lin & 7) * 8;
            *(uint4*)&Ah[r * LDT + c8] = *(const uint4*)&Ahi[(size_t)(m0 + r) * D_ + k0 + c8];
            *(uint4*)&Al[r * LDT + c8] = *(const uint4*)&Alo[(size_t)(m0 + r) * D_ + k0 + c8];
        }
        #pragma unroll
        for (int it = 0; it < 4; it++) {
            int lin = tid + it * 128;
            int r = lin >> 3, c8 = (lin & 7) * 8;
            *(uint4*)&Bh[r * LDT + c8] = *(const uint4*)&Bhi[(size_t)(n0 + r) * D_ + k0 + c8];
            *(uint4*)&Bl[r * LDT + c8] = *(const uint4*)&Blo[(size_t)(n0 + r) * D_ + k0 + c8];
        }
        __syncthreads();

        #pragma unroll
        for (int pass = 0; pass < 3; pass++) {
            const uint32_t ab = (pass < 2) ? s_ah : s_al;
            const uint32_t bb = (pass == 1) ? s_bl : s_bh;
            #pragma unroll
            for (int t = 0; t < 4; t++) {
                uint32_t a[4][4];
                #pragma unroll
                for (int i = 0; i < 4; i++)
                    lda_frag(a[i], ab, wr * 64 + i * 16, t * 16, lane);
                uint32_t b[16];
                ldb_frag2(b,      bb, wc * 32,      t * 16, lane);
                ldb_frag2(b + 4,  bb, wc * 32 + 16, t * 16, lane);
                ldb_frag2(b + 8,  bb, 0, 0, lane);   // placeholder overwritten below
                // (only 4 n8 tiles per warp: tiles 0..3 within wc*32..wc*32+31)
                #pragma unroll
                for (int i = 0; i < 4; i++) {
                    #pragma unroll
                    for (int j = 0; j < 4; j++)
                        mma16816(acc[i][j], a[i], &b[j * 2]);
                }
            }
        }
    }

    #pragma unroll
    for (int i = 0; i < 4; i++) {
        const int r0 = m0 + wr * 64 + i * 16 + (lane >> 2);
        #pragma unroll
        for (int j = 0; j < 4; j++) {
            const int col = n0 + wc * 32 + j * 8 + (lane & 3) * 2;
            const float b0 = bias[col], b1 = bias[col + 1];
            const float v00 = acc[i][j][0] + b0, v01 = acc[i][j][1] + b1;
            const float v10 = acc[i][j][2] + b0, v11 = acc[i][j][3] + b1;
            if (SCATTER) {
                #pragma unroll
                for (int u = 0; u < 2; u++) {
                    const int m = r0 + u * 8;
                    const float va = u ? v10 : v00, vb = u ? v11 : v01;
                    const int t   = col / D_;
                    const int rem = col - t * D_;
                    const int h   = rem >> 6, dd = rem & 63;
                    const int bb2 = m >> 11, s = m & (S_ - 1);
                    const size_t idx = ((size_t)(bb2 * H_ + h) * S_ + s) * DH + dd;
                    if (t == 2) {
                        *(float2*)&g_v[idx] = make_float2(va, vb);
                    } else {
                        uint32_t hh, ll;
                        pack_hl(va, vb, hh, ll);
                        if (t == 0) {
                            *(uint32_t*)&g_qh[idx] = hh;
                            *(uint32_t*)&g_ql[idx] = ll;
                        } else {
                            *(uint32_t*)&g_kh[idx] = hh;
                            *(uint32_t*)&g_kl[idx] = ll;
                        }
                    }
                }
            } else {
                *(float2*)&out[(size_t)r0 * D_ + col]       = make_float2(v00, v01);
                *(float2*)&out[(size_t)(r0 + 8) * D_ + col] = make_float2(v10, v11);
            }
        }
    }
}

// ---------------------------------------------------------------------------
// Flash attention on mma.sync: 64 q-rows per block, 4 warps x 16 rows.
// QK^T and PV both 3-term bf16 split; softmax fp32 in C-fragments.
// ---------------------------------------------------------------------------
#define ATT_SMEM (6 * 64 * LDT * 2 + 64 * 4)

__global__ void __launch_bounds__(128) attn_kernel(const int* __restrict__ mask) {
    extern __shared__ __nv_bfloat16 smb[];
    __nv_bfloat16* Qh = smb;
    __nv_bfloat16* Ql = Qh + 64 * LDT;
    __nv_bfloat16* Kh = Ql + 64 * LDT;
    __nv_bfloat16* Kl = Kh + 64 * LDT;
    __nv_bfloat16* Vh = Kl + 64 * LDT;
    __nv_bfloat16* Vl = Vh + 64 * LDT;
    float* mneg = (float*)(Vl + 64 * LDT);
    const uint32_t s_qh = smem_u32(Qh), s_ql = smem_u32(Ql);
    const uint32_t s_kh = smem_u32(Kh), s_kl = smem_u32(Kl);
    const uint32_t s_vh = smem_u32(Vh), s_vl = smem_u32(Vl);

    const int tid = threadIdx.x;
    const int wid = tid >> 5, lane = tid & 31;
    const int bh  = blockIdx.y;
    const int b   = bh / H_, h = bh - b * H_;
    const int q0  = blockIdx.x * 64;

    const __nv_bfloat16* qh_g = g_qh + (size_t)bh * S_ * DH;
    const __nv_bfloat16* ql_g = g_ql + (size_t)bh * S_ * DH;
    const __nv_bfloat16* kh_g = g_kh + (size_t)bh * S_ * DH;
    const __nv_bfloat16* kl_g = g_kl + (size_t)bh * S_ * DH;
    const float*         v_g  = g_v  + (size_t)bh * S_ * DH;

    // load Q tiles once
    #pragma unroll
    for (int it = 0; it < 4; it++) {
        int lin = tid + it * 128;
        int r = lin >> 3, c8 = (lin & 7) * 8;
        *(uint4*)&Qh[r * LDT + c8] = *(const uint4*)&qh_g[(size_t)(q0 + r) * DH + c8];
        *(uint4*)&Ql[r * LDT + c8] = *(const uint4*)&ql_g[(size_t)(q0 + r) * DH + c8];
    }

    const int lj = (lane & 3) * 2;
    const int ra = q0 + wid * 16 + (lane >> 2);
    const int rb = ra + 8;
    float m_a = -INFINITY, m_b = -INFINITY, l_a = 0.f, l_b = 0.f;
    float o[8][4] = {};

    for (int k0 = 0; k0 <= q0; k0 += 64) {
        __syncthreads();
        #pragma unroll
        for (int it = 0; it < 4; it++) {
            int lin = tid + it * 128;
            int r = lin >> 3, c8 = (lin & 7) * 8;
            *(uint4*)&Kh[r * LDT + c8] = *(const uint4*)&kh_g[(size_t)(k0 + r) * DH + c8];
            *(uint4*)&Kl[r * LDT + c8] = *(const uint4*)&kl_g[(size_t)(k0 + r) * DH + c8];
        }
        #pragma unroll
        for (int it = 0; it < 8; it++) {
            int lin = tid + it * 128;
            int r = lin >> 4, c4 = (lin & 15) * 4;
            float4 v = *(const float4*)&v_g[(size_t)(k0 + r) * DH + c4];
            uint32_t h01, l01, h23, l23;
            pack_hl(v.x, v.y, h01, l01);
            pack_hl(v.z, v.w, h23, l23);
            uint2 hv = make_uint2(h01, h23), lv = make_uint2(l01, l23);
            *(uint2*)&Vh[r * LDT + c4] = hv;
            *(uint2*)&Vl[r * LDT + c4] = lv;
        }
        if (tid < 64)
            mneg[tid] = (mask[b * S_ + k0 + tid] != 0) ? 0.f : -INFINITY;
        __syncthreads();

        // ---- S = Q @ K^T ----
        float s[8][4] = {};
        for (int pass = 0; pass < 3; pass++) {
            const uint32_t qb = (pass < 2) ? s_qh : s_ql;
            const uint32_t kb = (pass == 1) ? s_kl : s_kh;
            #pragma unroll
            for (int t = 0; t < 4; t++) {
                uint32_t a[4];
                lda_frag(a, qb, wid * 16, t * 16, lane);
                uint32_t bk[16];
                #pragma unroll
                for (int nb = 0; nb < 4; nb++)
                    ldb_frag2(bk + nb * 4, kb, nb * 16, t * 16, lane);
                #pragma unroll
                for (int j = 0; j < 8; j++)
                    mma16816(s[j], a, &bk[j * 2]);
            }
        }

        // ---- softmax ----
        float rmax_a = -INFINITY, rmax_b = -INFINITY;
        #pragma unroll
        for (int j = 0; j < 8; j++) {
            const int col = k0 + j * 8 + lj;
            const float mg0 = mneg[j * 8 + lj], mg1 = mneg[j * 8 + lj + 1];
            float v0 = s[j][0] * 0.125f + mg0; if (col     > ra) v0 = -INFINITY;
            float v1 = s[j][1] * 0.125f + mg1; if (col + 1 > ra) v1 = -INFINITY;
            float v2 = s[j][2] * 0.125f + mg0; if (col     > rb) v2 = -INFINITY;
            float v3 = s[j][3] * 0.125f + mg1; if (col + 1 > rb) v3 = -INFINITY;
            s[j][0] = v0; s[j][1] = v1; s[j][2] = v2; s[j][3] = v3;
            rmax_a = fmaxf(rmax_a, fmaxf(v0, v1));
            rmax_b = fmaxf(rmax_b, fmaxf(v2, v3));
        }
        #pragma unroll
        for (int st = 1; st < 4; st <<= 1) {
            rmax_a = fmaxf(rmax_a, __shfl_xor_sync(0xffffffffu, rmax_a, st));
            rmax_b = fmaxf(rmax_b, __shfl_xor_sync(0xffffffffu, rmax_b, st));
        }
        const float mna = fmaxf(m_a, rmax_a), mnb = fmaxf(m_b, rmax_b);
        const float aa = (mna == -INFINITY) ? 1.f : __expf(m_a - mna);
        const float ab = (mnb == -INFINITY) ? 1.f : __expf(m_b - mnb);
        float sum_a = 0.f, sum_b = 0.f;
        #pragma unroll
        for (int j = 0; j < 8; j++) {
            if (mna == -INFINITY) { s[j][0] = 0.f; s[j][1] = 0.f; }
            else {
                s[j][0] = __expf(s[j][0] - mna);
                s[j][1] = __expf(s[j][1] - mna);
                sum_a += s[j][0] + s[j][1];
            }
            if (mnb == -INFINITY) { s[j][2] = 0.f; s[j][3] = 0.f; }
            else {
                s[j][2] = __expf(s[j][2] - mnb);
                s[j][3] = __expf(s[j][3] - mnb);
                sum_b += s[j][2] + s[j][3];
            }
        }
        #pragma unroll
        for (int st = 1; st < 4; st <<= 1) {
            sum_a += __shfl_xor_sync(0xffffffffu, sum_a, st);
            sum_b += __shfl_xor_sync(0xffffffffu, sum_b, st);
        }
        l_a = l_a * aa + sum_a;  m_a = mna;
        l_b = l_b * ab + sum_b;  m_b = mnb;

        // ---- O = O*alpha + P @ V ----
        #pragma unroll
        for (int d = 0; d < 8; d++) {
            o[d][0] *= aa; o[d][1] *= aa;
            o[d][2] *= ab; o[d][3] *= ab;
        }
        #pragma unroll
        for (int t = 0; t < 4; t++) {
            uint32_t ph[4], pl[4];
            pack_hl(s[2 * t][0],     s[2 * t][1],     ph[0], pl[0]);
            pack_hl(s[2 * t][2],     s[2 * t][3],     ph[1], pl[1]);
            pack_hl(s[2 * t + 1][0], s[2 * t + 1][1], ph[2], pl[2]);
            pack_hl(s[2 * t + 1][2], s[2 * t + 1][3], ph[3], pl[3]);
            uint32_t bv[16];
            #pragma unroll
            for (int db = 0; db < 4; db++)
                ldbt_frag2(bv + db * 4, s_vh, t * 16, db * 16, lane);
            #pragma unroll
            for (int d = 0; d < 8; d++) mma16816(o[d], ph, &bv[d * 2]);
            #pragma unroll
            for (int d = 0; d < 8; d++) mma16816(o[d], pl, &bv[d * 2]);
            #pragma unroll
            for (int db = 0; db < 4; db++)
                ldbt_frag2(bv + db * 4, s_vl, t * 16, db * 16, lane);
            #pragma unroll
            for (int d = 0; d < 8; d++) mma16816(o[d], ph, &bv[d * 2]);
        }
    }

    const float inva = 1.f / l_a, invb = 1.f / l_b;
    #pragma unroll
    for (int d = 0; d < 8; d++) {
        const int col = h * DH + d * 8 + lj;
        *(float2*)&g_vw[((size_t)(b * S_) + ra) * D_ + col] =
            make_float2(o[d][0] * inva, o[d][1] * inva);
        *(float2*)&g_vw[((size_t)(b * S_) + rb) * D_ + col] =
            make_float2(o[d][2] * invb, o[d][3] * invb);
    }
}

// ---------------------------------------------------------------------------
extern "C" void kernel_launch(void* const* d_in, const int* in_sizes, int n_in,
                              void* d_out, int out_size) {
    const float* x    = (const float*)d_in[0];
    const float* Wqkv = (const float*)d_in[1];
    const float* bqkv = (const float*)d_in[2];
    const float* Wvw  = (const float*)d_in[3];
    const float* bvw  = (const float*)d_in[4];
    const int*   mask = (const int*)d_in[5];
    float* out = (float*)d_out;

    cudaFuncSetAttribute(mma_gemm<1>, cudaFuncAttributeMaxDynamicSharedMemorySize, PROJ_SMEM);
    cudaFuncSetAttribute(mma_gemm<0>, cudaFuncAttributeMaxDynamicSharedMemorySize, PROJ_SMEM);
    cudaFuncSetAttribute(attn_kernel, cudaFuncAttributeMaxDynamicSharedMemorySize, ATT_SMEM);

    __nv_bfloat16 *xh, *xl, *wqh, *wql, *wvh, *wvl, *vwh, *vwl;
    float* vwf;
    cudaGetSymbolAddress((void**)&xh,  g_xh);  cudaGetSymbolAddress((void**)&xl,  g_xl);
    cudaGetSymbolAddress((void**)&wqh, g_wqh); cudaGetSymbolAddress((void**)&wql, g_wql);
    cudaGetSymbolAddress((void**)&wvh, g_wvh); cudaGetSymbolAddress((void**)&wvl, g_wvl);
    cudaGetSymbolAddress((void**)&vwh, g_vwh); cudaGetSymbolAddress((void**)&vwl, g_vwl);
    cudaGetSymbolAddress((void**)&vwf, g_vw);

    split_kernel<<<(M_ * D_ / 4 + 255) / 256, 256>>>(x, xh, xl, M_ * D_);
    tsplit_kernel<<<dim3(N_QKV / 32, D_ / 32), dim3(32, 8)>>>(Wqkv, wqh, wql, D_, N_QKV);
    tsplit_kernel<<<dim3(D_ / 32, D_ / 32), dim3(32, 8)>>>(Wvw, wvh, wvl, D_, D_);

    mma_gemm<1><<<dim3(N_QKV / 64, M_ / 128), 128, PROJ_SMEM>>>(
        xh, xl, wqh, wql, bqkv, nullptr, N_QKV);

    attn_kernel<<<dim3(S_ / 64, B_ * H_), 128, ATT_SMEM>>>(mask);

    split_kernel<<<(M_ * D_ / 4 + 255) / 256, 256>>>(vwf, vwh, vwl, M_ * D_);
    mma_gemm<0><<<dim3(D_ / 64, M_ / 128), 128, PROJ_SMEM>>>(
        vwh, vwl, wvh, wvl, bvw, out, D_);
}

// round 5
// speedup vs baseline: 3.5450x; 1.0349x over previous
#include <cuda_runtime.h>
#include <cuda_bf16.h>
#include <math.h>
#include <stdint.h>

#define B_  2
#define S_  2048
#define D_  768
#define H_  12
#define DH  64
#define M_  (B_ * S_)      // 4096
#define N_QKV (3 * D_)     // 2304
#define LDT 72             // smem row stride (bf16), conflict-free ldmatrix

// ---------------- scratch (allocation-free) ----------------
__device__ __nv_bfloat16 g_qh[B_ * H_ * S_ * DH], g_ql[B_ * H_ * S_ * DH];
__device__ __nv_bfloat16 g_kh[B_ * H_ * S_ * DH], g_kl[B_ * H_ * S_ * DH];
__device__ __nv_bfloat16 g_vh[B_ * H_ * S_ * DH], g_vl[B_ * H_ * S_ * DH];

__device__ __nv_bfloat16 g_xh[M_ * D_],     g_xl[M_ * D_];
__device__ __nv_bfloat16 g_wqh[N_QKV * D_], g_wql[N_QKV * D_];   // W_qkv^T [N,K]
__device__ __nv_bfloat16 g_wvh[D_ * D_],    g_wvl[D_ * D_];      // W_vw^T  [N,K]
__device__ __nv_bfloat16 g_vwh[M_ * D_],    g_vwl[M_ * D_];

// ---------------- helpers ----------------
__device__ __forceinline__ uint32_t smem_u32(const void* p) {
    uint32_t a;
    asm("{ .reg .u64 t; cvta.to.shared.u64 t, %1; cvt.u32.u64 %0, t; }"
        : "=r"(a) : "l"(p));
    return a;
}
__device__ __forceinline__ void cp16(uint32_t s, const void* g) {
    asm volatile("cp.async.cg.shared.global [%0], [%1], 16;"
                 :: "r"(s), "l"(g) : "memory");
}
#define CP_COMMIT() asm volatile("cp.async.commit_group;" ::: "memory")
#define CP_WAIT0()  asm volatile("cp.async.wait_group 0;" ::: "memory")

__device__ __forceinline__ void ldsm4(uint32_t* r, uint32_t a) {
    asm volatile("ldmatrix.sync.aligned.m8n8.x4.shared.b16 {%0,%1,%2,%3}, [%4];"
        : "=r"(r[0]), "=r"(r[1]), "=r"(r[2]), "=r"(r[3]) : "r"(a));
}
__device__ __forceinline__ void ldsm4t(uint32_t* r, uint32_t a) {
    asm volatile("ldmatrix.sync.aligned.m8n8.x4.trans.shared.b16 {%0,%1,%2,%3}, [%4];"
        : "=r"(r[0]), "=r"(r[1]), "=r"(r[2]), "=r"(r[3]) : "r"(a));
}
__device__ __forceinline__ void mma16816(float* c, const uint32_t* a, const uint32_t* b) {
    asm volatile("mma.sync.aligned.m16n8k16.row.col.f32.bf16.bf16.f32 "
        "{%0,%1,%2,%3}, {%4,%5,%6,%7}, {%8,%9}, {%0,%1,%2,%3};"
        : "+f"(c[0]), "+f"(c[1]), "+f"(c[2]), "+f"(c[3])
        : "r"(a[0]), "r"(a[1]), "r"(a[2]), "r"(a[3]), "r"(b[0]), "r"(b[1]));
}
__device__ __forceinline__ void lda_frag(uint32_t* r, uint32_t base, int row0, int k0, int lane) {
    uint32_t a = base + (uint32_t)(((row0 + (lane & 15)) * LDT + k0 + ((lane >> 4) << 3)) << 1);
    ldsm4(r, a);
}
__device__ __forceinline__ void ldb_frag2(uint32_t* r, uint32_t base, int n0, int k0, int lane) {
    int g = lane >> 3;
    uint32_t a = base + (uint32_t)(((n0 + ((g & 2) << 2) + (lane & 7)) * LDT
                                    + k0 + ((g & 1) << 3)) << 1);
    ldsm4(r, a);
}
__device__ __forceinline__ void ldbt_frag2(uint32_t* r, uint32_t base, int key0, int dh0, int lane) {
    int g = lane >> 3;
    uint32_t a = base + (uint32_t)(((key0 + ((g & 1) << 3) + (lane & 7)) * LDT
                                    + dh0 + ((g & 2) << 2)) << 1);
    ldsm4t(r, a);
}
__device__ __forceinline__ void pack_hl(float v0, float v1, uint32_t& hi, uint32_t& lo) {
    __nv_bfloat16 h0 = __float2bfloat16(v0), h1 = __float2bfloat16(v1);
    __nv_bfloat162 hh(h0, h1);
    hi = *(uint32_t*)&hh;
    __nv_bfloat16 l0 = __float2bfloat16(v0 - __bfloat162float(h0));
    __nv_bfloat16 l1 = __float2bfloat16(v1 - __bfloat162float(h1));
    __nv_bfloat162 ll(l0, l1);
    lo = *(uint32_t*)&ll;
}

// ---------------------------------------------------------------------------
__global__ void split_kernel(const float* __restrict__ src,
                             __nv_bfloat16* __restrict__ hi,
                             __nv_bfloat16* __restrict__ lo, int n) {
    int i = (blockIdx.x * blockDim.x + threadIdx.x) * 4;
    if (i >= n) return;
    float4 v = *(const float4*)(src + i);
    uint32_t h01, l01, h23, l23;
    pack_hl(v.x, v.y, h01, l01);
    pack_hl(v.z, v.w, h23, l23);
    *(uint32_t*)(hi + i)     = h01;
    *(uint32_t*)(hi + i + 2) = h23;
    *(uint32_t*)(lo + i)     = l01;
    *(uint32_t*)(lo + i + 2) = l23;
}

__global__ void tsplit_kernel(const float* __restrict__ W,
                              __nv_bfloat16* __restrict__ hi,
                              __nv_bfloat16* __restrict__ lo, int K, int N) {
    __shared__ float t[32][33];
    int n0 = blockIdx.x * 32, k0 = blockIdx.y * 32;
    int tx = threadIdx.x, ty = threadIdx.y;
    #pragma unroll
    for (int jj = 0; jj < 4; jj++)
        t[ty + jj * 8][tx] = W[(size_t)(k0 + ty + jj * 8) * N + n0 + tx];
    __syncthreads();
    #pragma unroll
    for (int jj = 0; jj < 4; jj++) {
        float v = t[tx][ty + jj * 8];
        int n = n0 + ty + jj * 8, k = k0 + tx;
        __nv_bfloat16 h = __float2bfloat16(v);
        hi[(size_t)n * K + k] = h;
        lo[(size_t)n * K + k] = __float2bfloat16(v - __bfloat162float(h));
    }
}

// ---------------------------------------------------------------------------
// Projection GEMM, cp.async double-buffered. Block tile 128x64, 4 warps
// (warp = 64x32), K chunks of 64, 3-term bf16 split.
// ---------------------------------------------------------------------------
#define PST (2 * 128 * LDT + 2 * 64 * LDT)       // bf16 elems per stage
#define PROJ_SMEM (2 * PST * 2)                  // 110,592 bytes

template<int SCATTER>
__global__ void __launch_bounds__(128) mma_gemm(
    const __nv_bfloat16* __restrict__ Ahi, const __nv_bfloat16* __restrict__ Alo,
    const __nv_bfloat16* __restrict__ Bhi, const __nv_bfloat16* __restrict__ Blo,
    const float* __restrict__ bias, float* __restrict__ out) {
    extern __shared__ __nv_bfloat16 sm[];
    const uint32_t sbase = smem_u32(sm);
    const int tid  = threadIdx.x;
    const int wid  = tid >> 5, lane = tid & 31;
    const int wr   = wid >> 1, wc = wid & 1;
    const int m0   = blockIdx.y * 128;
    const int n0   = blockIdx.x * 64;

    auto prefetch = [&](int st, int k0) {
        const uint32_t b = sbase + (uint32_t)(st * PST * 2);
        #pragma unroll
        for (int it = 0; it < 8; it++) {
            int lin = tid + it * 128;
            int r = lin >> 3, c8 = (lin & 7) * 8;
            uint32_t so = (uint32_t)((r * LDT + c8) << 1);
            cp16(b + so, Ahi + (size_t)(m0 + r) * D_ + k0 + c8);
            cp16(b + (uint32_t)(128 * LDT * 2) + so,
                 Alo + (size_t)(m0 + r) * D_ + k0 + c8);
        }
        #pragma unroll
        for (int it = 0; it < 4; it++) {
            int lin = tid + it * 128;
            int r = lin >> 3, c8 = (lin & 7) * 8;
            uint32_t so = (uint32_t)((r * LDT + c8) << 1);
            cp16(b + (uint32_t)(256 * LDT * 2) + so,
                 Bhi + (size_t)(n0 + r) * D_ + k0 + c8);
            cp16(b + (uint32_t)(320 * LDT * 2) + so,
                 Blo + (size_t)(n0 + r) * D_ + k0 + c8);
        }
        CP_COMMIT();
    };

    float acc[4][4][4] = {};
    prefetch(0, 0);

    for (int c = 0; c < 12; c++) {
        CP_WAIT0();
        __syncthreads();
        if (c < 11) prefetch((c + 1) & 1, (c + 1) * 64);

        const uint32_t b  = sbase + (uint32_t)((c & 1) * PST * 2);
        const uint32_t s_ah = b;
        const uint32_t s_al = b + 128 * LDT * 2;
        const uint32_t s_bh = b + 256 * LDT * 2;
        const uint32_t s_bl = b + 320 * LDT * 2;

        #pragma unroll
        for (int t = 0; t < 4; t++) {
            uint32_t ah[4][4], al[4][4], bh[8], bl[8];
            #pragma unroll
            for (int i = 0; i < 4; i++) {
                lda_frag(ah[i], s_ah, wr * 64 + i * 16, t * 16, lane);
                lda_frag(al[i], s_al, wr * 64 + i * 16, t * 16, lane);
            }
            ldb_frag2(bh,     s_bh, wc * 32,      t * 16, lane);
            ldb_frag2(bh + 4, s_bh, wc * 32 + 16, t * 16, lane);
            ldb_frag2(bl,     s_bl, wc * 32,      t * 16, lane);
            ldb_frag2(bl + 4, s_bl, wc * 32 + 16, t * 16, lane);
            #pragma unroll
            for (int i = 0; i < 4; i++)
                #pragma unroll
                for (int j = 0; j < 4; j++) {
                    mma16816(acc[i][j], ah[i], &bh[j * 2]);
                    mma16816(acc[i][j], ah[i], &bl[j * 2]);
                    mma16816(acc[i][j], al[i], &bh[j * 2]);
                }
        }
    }

    #pragma unroll
    for (int i = 0; i < 4; i++) {
        const int r0 = m0 + wr * 64 + i * 16 + (lane >> 2);
        #pragma unroll
        for (int j = 0; j < 4; j++) {
            const int col = n0 + wc * 32 + j * 8 + (lane & 3) * 2;
            const float b0 = bias[col], b1 = bias[col + 1];
            const float v00 = acc[i][j][0] + b0, v01 = acc[i][j][1] + b1;
            const float v10 = acc[i][j][2] + b0, v11 = acc[i][j][3] + b1;
            if (SCATTER) {
                const int t   = col / D_;
                const int rem = col - t * D_;
                const int h   = rem >> 6, dd = rem & 63;
                #pragma unroll
                for (int u = 0; u < 2; u++) {
                    const int m = r0 + u * 8;
                    const float va = u ? v10 : v00, vb = u ? v11 : v01;
                    const int bb2 = m >> 11, s = m & (S_ - 1);
                    const size_t idx = ((size_t)(bb2 * H_ + h) * S_ + s) * DH + dd;
                    uint32_t hh, ll;
                    pack_hl(va, vb, hh, ll);
                    if (t == 0) {
                        *(uint32_t*)&g_qh[idx] = hh;
                        *(uint32_t*)&g_ql[idx] = ll;
                    } else if (t == 1) {
                        *(uint32_t*)&g_kh[idx] = hh;
                        *(uint32_t*)&g_kl[idx] = ll;
                    } else {
                        *(uint32_t*)&g_vh[idx] = hh;
                        *(uint32_t*)&g_vl[idx] = ll;
                    }
                }
            } else {
                *(float2*)&out[(size_t)r0 * D_ + col]       = make_float2(v00, v01);
                *(float2*)&out[(size_t)(r0 + 8) * D_ + col] = make_float2(v10, v11);
            }
        }
    }
}

// ---------------------------------------------------------------------------
// Flash attention: 64 q-rows/block, 4 warps, cp.async double-buffered K/V,
// Q fragments hoisted, epilogue writes vw hi/lo bf16 directly.
// ---------------------------------------------------------------------------
#define AST (4 * 64 * LDT)                              // bf16 elems per stage
#define ATT_SMEM ((2 * 64 * LDT + 2 * AST) * 2 + 2 * 64 * 4)

__global__ void __launch_bounds__(128) attn_kernel(const int* __restrict__ mask) {
    extern __shared__ __nv_bfloat16 smb[];
    __nv_bfloat16* Qh = smb;                     // 64xLDT
    __nv_bfloat16* Ql = Qh + 64 * LDT;
    __nv_bfloat16* ST = Ql + 64 * LDT;           // 2 stages x (Kh,Kl,Vh,Vl)
    float* mneg = (float*)(ST + 2 * AST);        // [2][64]
    const uint32_t s_qh = smem_u32(Qh), s_ql = smem_u32(Ql);
    const uint32_t s_st = smem_u32(ST);

    const int tid = threadIdx.x;
    const int wid = tid >> 5, lane = tid & 31;
    const int bh  = blockIdx.y;
    const int b   = bh / H_, h = bh - b * H_;
    const int q0  = blockIdx.x * 64;

    const __nv_bfloat16* qh_g = g_qh + (size_t)bh * S_ * DH;
    const __nv_bfloat16* ql_g = g_ql + (size_t)bh * S_ * DH;
    const __nv_bfloat16* kh_g = g_kh + (size_t)bh * S_ * DH;
    const __nv_bfloat16* kl_g = g_kl + (size_t)bh * S_ * DH;
    const __nv_bfloat16* vh_g = g_vh + (size_t)bh * S_ * DH;
    const __nv_bfloat16* vl_g = g_vl + (size_t)bh * S_ * DH;

    auto prefetch = [&](int st, int k0) {
        const uint32_t base = s_st + (uint32_t)(st * AST * 2);
        #pragma unroll
        for (int it = 0; it < 4; it++) {
            int lin = tid + it * 128;
            int r = lin >> 3, c8 = (lin & 7) * 8;
            uint32_t so = (uint32_t)((r * LDT + c8) << 1);
            const size_t g = (size_t)(k0 + r) * DH + c8;
            cp16(base + so,                                kh_g + g);
            cp16(base + (uint32_t)(64 * LDT * 2)     + so, kl_g + g);
            cp16(base + (uint32_t)(2 * 64 * LDT * 2) + so, vh_g + g);
            cp16(base + (uint32_t)(3 * 64 * LDT * 2) + so, vl_g + g);
        }
        if (tid < 64)
            mneg[st * 64 + tid] = (mask[b * S_ + k0 + tid] != 0) ? 0.f : -INFINITY;
        CP_COMMIT();
    };

    // load Q tiles once
    #pragma unroll
    for (int it = 0; it < 4; it++) {
        int lin = tid + it * 128;
        int r = lin >> 3, c8 = (lin & 7) * 8;
        *(uint4*)&Qh[r * LDT + c8] = *(const uint4*)&qh_g[(size_t)(q0 + r) * DH + c8];
        *(uint4*)&Ql[r * LDT + c8] = *(const uint4*)&ql_g[(size_t)(q0 + r) * DH + c8];
    }
    prefetch(0, 0);
    __syncthreads();

    // hoist Q fragments
    uint32_t qfh[4][4], qfl[4][4];
    #pragma unroll
    for (int t = 0; t < 4; t++) {
        lda_frag(qfh[t], s_qh, wid * 16, t * 16, lane);
        lda_frag(qfl[t], s_ql, wid * 16, t * 16, lane);
    }

    const int lj = (lane & 3) * 2;
    const int ra = q0 + wid * 16 + (lane >> 2);
    const int rb = ra + 8;
    float m_a = -INFINITY, m_b = -INFINITY, l_a = 0.f, l_b = 0.f;
    float o[8][4] = {};
    const int nch = (q0 >> 6) + 1;

    for (int c = 0; c < nch; c++) {
        CP_WAIT0();
        __syncthreads();
        if (c + 1 < nch) prefetch((c + 1) & 1, (c + 1) * 64);

        const int st = c & 1;
        const int k0 = c * 64;
        const uint32_t base = s_st + (uint32_t)(st * AST * 2);
        const uint32_t s_kh = base;
        const uint32_t s_kl = base + 64 * LDT * 2;
        const uint32_t s_vh = base + 2 * 64 * LDT * 2;
        const uint32_t s_vl = base + 3 * 64 * LDT * 2;
        const float* mg = mneg + st * 64;

        // ---- S = Q @ K^T ----
        float s[8][4] = {};
        #pragma unroll
        for (int t = 0; t < 4; t++) {
            uint32_t bkh[16], bkl[16];
            #pragma unroll
            for (int nb = 0; nb < 4; nb++) {
                ldb_frag2(bkh + nb * 4, s_kh, nb * 16, t * 16, lane);
                ldb_frag2(bkl + nb * 4, s_kl, nb * 16, t * 16, lane);
            }
            #pragma unroll
            for (int j = 0; j < 8; j++) {
                mma16816(s[j], qfh[t], &bkh[j * 2]);
                mma16816(s[j], qfh[t], &bkl[j * 2]);
                mma16816(s[j], qfl[t], &bkh[j * 2]);
            }
        }

        // ---- softmax ----
        float rmax_a = -INFINITY, rmax_b = -INFINITY;
        #pragma unroll
        for (int j = 0; j < 8; j++) {
            const int col = k0 + j * 8 + lj;
            const float mg0 = mg[j * 8 + lj], mg1 = mg[j * 8 + lj + 1];
            float v0 = s[j][0] * 0.125f + mg0; if (col     > ra) v0 = -INFINITY;
            float v1 = s[j][1] * 0.125f + mg1; if (col + 1 > ra) v1 = -INFINITY;
            float v2 = s[j][2] * 0.125f + mg0; if (col     > rb) v2 = -INFINITY;
            float v3 = s[j][3] * 0.125f + mg1; if (col + 1 > rb) v3 = -INFINITY;
            s[j][0] = v0; s[j][1] = v1; s[j][2] = v2; s[j][3] = v3;
            rmax_a = fmaxf(rmax_a, fmaxf(v0, v1));
            rmax_b = fmaxf(rmax_b, fmaxf(v2, v3));
        }
        #pragma unroll
        for (int st2 = 1; st2 < 4; st2 <<= 1) {
            rmax_a = fmaxf(rmax_a, __shfl_xor_sync(0xffffffffu, rmax_a, st2));
            rmax_b = fmaxf(rmax_b, __shfl_xor_sync(0xffffffffu, rmax_b, st2));
        }
        const float mna = fmaxf(m_a, rmax_a), mnb = fmaxf(m_b, rmax_b);
        const float aa = (mna == -INFINITY) ? 1.f : __expf(m_a - mna);
        const float ab = (mnb == -INFINITY) ? 1.f : __expf(m_b - mnb);
        float sum_a = 0.f, sum_b = 0.f;
        #pragma unroll
        for (int j = 0; j < 8; j++) {
            if (mna == -INFINITY) { s[j][0] = 0.f; s[j][1] = 0.f; }
            else {
                s[j][0] = __expf(s[j][0] - mna);
                s[j][1] = __expf(s[j][1] - mna);
                sum_a += s[j][0] + s[j][1];
            }
            if (mnb == -INFINITY) { s[j][2] = 0.f; s[j][3] = 0.f; }
            else {
                s[j][2] = __expf(s[j][2] - mnb);
                s[j][3] = __expf(s[j][3] - mnb);
                sum_b += s[j][2] + s[j][3];
            }
        }
        #pragma unroll
        for (int st2 = 1; st2 < 4; st2 <<= 1) {
            sum_a += __shfl_xor_sync(0xffffffffu, sum_a, st2);
            sum_b += __shfl_xor_sync(0xffffffffu, sum_b, st2);
        }
        l_a = l_a * aa + sum_a;  m_a = mna;
        l_b = l_b * ab + sum_b;  m_b = mnb;

        // ---- O = O*alpha + P @ V ----
        #pragma unroll
        for (int d = 0; d < 8; d++) {
            o[d][0] *= aa; o[d][1] *= aa;
            o[d][2] *= ab; o[d][3] *= ab;
        }
        #pragma unroll
        for (int t = 0; t < 4; t++) {
            uint32_t ph[4], pl[4];
            pack_hl(s[2 * t][0],     s[2 * t][1],     ph[0], pl[0]);
            pack_hl(s[2 * t][2],     s[2 * t][3],     ph[1], pl[1]);
            pack_hl(s[2 * t + 1][0], s[2 * t + 1][1], ph[2], pl[2]);
            pack_hl(s[2 * t + 1][2], s[2 * t + 1][3], ph[3], pl[3]);
            uint32_t bv[16];
            #pragma unroll
            for (int db = 0; db < 4; db++)
                ldbt_frag2(bv + db * 4, s_vh, t * 16, db * 16, lane);
            #pragma unroll
            for (int d = 0; d < 8; d++) mma16816(o[d], ph, &bv[d * 2]);
            #pragma unroll
            for (int d = 0; d < 8; d++) mma16816(o[d], pl, &bv[d * 2]);
            #pragma unroll
            for (int db = 0; db < 4; db++)
                ldbt_frag2(bv + db * 4, s_vl, t * 16, db * 16, lane);
            #pragma unroll
            for (int d = 0; d < 8; d++) mma16816(o[d], ph, &bv[d * 2]);
        }
    }

    // epilogue: write hi/lo bf16 directly (feeds out_gemm)
    const float inva = 1.f / l_a, invb = 1.f / l_b;
    #pragma unroll
    for (int d = 0; d < 8; d++) {
        const int col = h * DH + d * 8 + lj;
        uint32_t hh, ll;
        pack_hl(o[d][0] * inva, o[d][1] * inva, hh, ll);
        *(uint32_t*)&g_vwh[((size_t)(b * S_) + ra) * D_ + col] = hh;
        *(uint32_t*)&g_vwl[((size_t)(b * S_) + ra) * D_ + col] = ll;
        pack_hl(o[d][2] * invb, o[d][3] * invb, hh, ll);
        *(uint32_t*)&g_vwh[((size_t)(b * S_) + rb) * D_ + col] = hh;
        *(uint32_t*)&g_vwl[((size_t)(b * S_) + rb) * D_ + col] = ll;
    }
}

// ---------------------------------------------------------------------------
extern "C" void kernel_launch(void* const* d_in, const int* in_sizes, int n_in,
                              void* d_out, int out_size) {
    const float* x    = (const float*)d_in[0];
    const float* Wqkv = (const float*)d_in[1];
    const float* bqkv = (const float*)d_in[2];
    const float* Wvw  = (const float*)d_in[3];
    const float* bvw  = (const float*)d_in[4];
    const int*   mask = (const int*)d_in[5];
    float* out = (float*)d_out;

    cudaFuncSetAttribute(mma_gemm<1>, cudaFuncAttributeMaxDynamicSharedMemorySize, PROJ_SMEM);
    cudaFuncSetAttribute(mma_gemm<0>, cudaFuncAttributeMaxDynamicSharedMemorySize, PROJ_SMEM);
    cudaFuncSetAttribute(attn_kernel, cudaFuncAttributeMaxDynamicSharedMemorySize, ATT_SMEM);

    __nv_bfloat16 *xh, *xl, *wqh, *wql, *wvh, *wvl, *vwh, *vwl;
    cudaGetSymbolAddress((void**)&xh,  g_xh);  cudaGetSymbolAddress((void**)&xl,  g_xl);
    cudaGetSymbolAddress((void**)&wqh, g_wqh); cudaGetSymbolAddress((void**)&wql, g_wql);
    cudaGetSymbolAddress((void**)&wvh, g_wvh); cudaGetSymbolAddress((void**)&wvl, g_wvl);
    cudaGetSymbolAddress((void**)&vwh, g_vwh); cudaGetSymbolAddress((void**)&vwl, g_vwl);

    split_kernel<<<(M_ * D_ / 4 + 255) / 256, 256>>>(x, xh, xl, M_ * D_);
    tsplit_kernel<<<dim3(N_QKV / 32, D_ / 32), dim3(32, 8)>>>(Wqkv, wqh, wql, D_, N_QKV);
    tsplit_kernel<<<dim3(D_ / 32, D_ / 32), dim3(32, 8)>>>(Wvw, wvh, wvl, D_, D_);

    mma_gemm<1><<<dim3(N_QKV / 64, M_ / 128), 128, PROJ_SMEM>>>(
        xh, xl, wqh, wql, bqkv, nullptr);

    attn_kernel<<<dim3(S_ / 64, B_ * H_), 128, ATT_SMEM>>>(mask);

    mma_gemm<0><<<dim3(D_ / 64, M_ / 128), 128, PROJ_SMEM>>>(
        vwh, vwl, wvh, wvl, bvw, out);
}